// round 5
// baseline (speedup 1.0000x reference)
#include <cuda_runtime.h>
#include <cuda_fp16.h>
#include <cstdint>

#define BB   64
#define TT   128
#define VV   10000
#define EE   300
#define HH   1024
#define G4   4096
#define TM1  127
#define MROWS 8128
#define KE   320        // padded E
#define NPADV 10112     // padded V (79*128)

typedef __half fp16;

// ---------------- scratch (device globals) -----------------------------------
__device__ __align__(16) fp16  g_emb [MROWS * KE];
__device__ __align__(16) float g_pre0[(size_t)MROWS * G4];     // gate-interleaved cols
__device__ __align__(16) float g_gp0 [4 * BB * G4];            // K-split partials (tile-compact)
__device__ __align__(16) float g_gp1 [4 * BB * G4];
__device__ __align__(16) float g_c0  [BB * HH];
__device__ __align__(16) float g_c1  [BB * HH];
__device__ __align__(16) fp16  g_h0H [2 * BB * HH];            // parity x [64][1024] hi
__device__ __align__(16) fp16  g_h0L [2 * BB * HH];
__device__ __align__(16) fp16  g_h1H [2 * BB * HH];
__device__ __align__(16) fp16  g_h1L [2 * BB * HH];
__device__ __align__(16) fp16  g_H1  [(size_t)MROWS * HH];
__device__ __align__(16) fp16  g_wih0T[G4 * KE];               // [4096 ilv][320]
__device__ __align__(16) fp16  g_whh0T[G4 * HH];               // [4096 ilv][1024]
__device__ __align__(16) fp16  g_w1T [G4 * 2048];              // [4096 ilv][2048]
__device__ __align__(16) fp16  g_woutT[(size_t)NPADV * HH];
__device__ __align__(16) float g_b0i[G4];
__device__ __align__(16) float g_b1i[G4];
__device__ __align__(16) float g_rowsum[MROWS];
__device__ float g_lossb[BB];
__device__ int   g_cnt[64];                                    // [2 layers][32 ntiles]

// ---------------- fast math (FMA-only exp) -----------------------------------
__device__ __forceinline__ float fexp(float x) {
    x = fminf(x, 88.0f);
    if (x < -87.0f) return 0.0f;
    float t = fmaf(x, 1.4426950408889634f, 12582912.0f);
    float n = t - 12582912.0f;
    int   e = __float_as_int(t) - 0x4B400000;
    float r = fmaf(n, -0.693359375f, x);
    r = fmaf(n, 2.1219444e-4f, r);
    float p = fmaf(8.3333333e-3f, r, 4.1666668e-2f);
    p = fmaf(p, r, 1.6666667e-1f);
    p = fmaf(p, r, 0.5f);
    p = fmaf(p, r, 1.0f);
    p = fmaf(p, r, 1.0f);
    return __int_as_float(__float_as_int(p) + (e << 23));
}
__device__ __forceinline__ float sigf(float x)  { return 1.0f / (1.0f + fexp(-x)); }
__device__ __forceinline__ float tanhf_(float x){ return fmaf(2.0f, sigf(2.0f * x), -1.0f); }

// ---------------- ptx helpers -------------------------------------------------
__device__ __forceinline__ uint32_t smem_u32(const void* p) {
    uint32_t a;
    asm("{ .reg .u64 t; cvta.to.shared.u64 t, %1; cvt.u32.u64 %0, t; }" : "=r"(a) : "l"(p));
    return a;
}
__device__ __forceinline__ void cpa16(uint32_t dst, const void* src, int valid) {
    asm volatile("cp.async.cg.shared.global [%0], [%1], 16, %2;"
                 :: "r"(dst), "l"(src), "r"(valid) : "memory");
}
#define CP_COMMIT()  asm volatile("cp.async.commit_group;" ::: "memory")
#define CP_WAIT(n)   asm volatile("cp.async.wait_group %0;" :: "n"(n) : "memory")

__device__ __forceinline__ void ldm4(uint32_t* r, uint32_t addr) {
    asm volatile("ldmatrix.sync.aligned.m8n8.x4.shared.b16 {%0,%1,%2,%3}, [%4];"
                 : "=r"(r[0]), "=r"(r[1]), "=r"(r[2]), "=r"(r[3]) : "r"(addr));
}
__device__ __forceinline__ void mma16816(float* d, const uint32_t* a, const uint32_t* b) {
    asm volatile(
        "mma.sync.aligned.m16n8k16.row.col.f32.f16.f16.f32 "
        "{%0,%1,%2,%3}, {%4,%5,%6,%7}, {%8,%9}, {%0,%1,%2,%3};"
        : "+f"(d[0]), "+f"(d[1]), "+f"(d[2]), "+f"(d[3])
        : "r"(a[0]), "r"(a[1]), "r"(a[2]), "r"(a[3]), "r"(b[0]), "r"(b[1]));
}
#define SW128(x) ((x) ^ (((x) >> 3) & 0x70))

// ---------------- init / gather / prep ---------------------------------------
__global__ void zero_state() {
    int idx = blockIdx.x * 256 + threadIdx.x;        // 131072 threads
    fp16 z = __float2half_rn(0.0f);
    g_h0H[idx] = z; g_h0L[idx] = z; g_h1H[idx] = z; g_h1L[idx] = z;
    if (idx < BB * HH) { g_c0[idx] = 0.f; g_c1[idx] = 0.f; }
    if (idx < MROWS) g_rowsum[idx] = 0.f;
    if (idx < BB) g_lossb[idx] = 0.f;
    if (idx < 64) g_cnt[idx] = 0;
}

__global__ void gather_emb(const int* __restrict__ sent, const float* __restrict__ wordvec) {
    int idx = blockIdx.x * 256 + threadIdx.x;
    if (idx >= MROWS * KE) return;
    int r = idx / KE, k = idx - r * KE;
    int t = r >> 6, b = r & 63;
    float v = 0.f;
    if (k < EE) { int w = sent[b * TT + t]; v = wordvec[(size_t)w * EE + k]; }
    g_emb[idx] = __float2half_rn(v);
}

// transpose: W fp32 [Ksrc, Nsrc] -> O fp16 [Npad][Kpad] at col offset koff
// ileave: output row n_out = 4*(n&1023) + (n>>10)  (gate interleave)
__global__ void prep_T(const float* __restrict__ W, int Ksrc, int Nsrc,
                       fp16* __restrict__ O,
                       int Kpad, int koff, int Kspan, int Npad, int ileave) {
    __shared__ float ts[32][33];
    int k0 = blockIdx.x * 32, n0 = blockIdx.y * 32;
    int tx = threadIdx.x, ty = threadIdx.y;
#pragma unroll
    for (int i = 0; i < 4; i++) {
        int k = k0 + ty + i * 8, n = n0 + tx;
        float v = (k < Ksrc && n < Nsrc) ? W[(size_t)k * Nsrc + n] : 0.f;
        ts[ty + i * 8][tx] = v;
    }
    __syncthreads();
#pragma unroll
    for (int i = 0; i < 4; i++) {
        int n = n0 + ty + i * 8, k = k0 + tx;
        if (n < Npad && k < Kspan) {
            int n_out = ileave ? (((n & 1023) << 2) + (n >> 10)) : n;
            O[(size_t)n_out * Kpad + koff + k] = __float2half_rn(ts[tx][ty + i * 8]);
        }
    }
}

__global__ void prep_bias(const float* __restrict__ b0, const float* __restrict__ b1) {
    int j = blockIdx.x * 256 + threadIdx.x;
    if (j >= G4) return;
    int n_out = ((j & 1023) << 2) + (j >> 10);
    g_b0i[n_out] = b0[j];
    g_b1i[n_out] = b1[j];
}

// ---------------- big GEMM (MT=2, single-pass fp16, 3-stage) ------------------
// C[M,N] = A[M,K] @ B^T[N,K] + bias; mode2 also stores exp-rowsums
#define BSTAGE 32768
__device__ __forceinline__ void ldstage_b(
    uint32_t st, int tid, int m0, int n0, int k0,
    const fp16* A, int lda, const fp16* B, int ldb, int Mreal)
{
#pragma unroll
    for (int e = tid; e < 1024; e += 256) {
        int r = e >> 3, c = e & 7;
        uint32_t sw = SW128((uint32_t)(r * 128 + c * 16));
        int gr = m0 + r;
        int ok = 16;
        if (gr >= Mreal) { ok = 0; gr = 0; }
        cpa16(st + sw, A + (size_t)gr * lda + k0 + c * 8, ok);
    }
#pragma unroll
    for (int e = tid; e < 1024; e += 256) {
        int r = e >> 3, c = e & 7;
        uint32_t sw = SW128((uint32_t)(r * 128 + c * 16));
        cpa16(st + 16384 + sw, B + (size_t)(n0 + r) * ldb + k0 + c * 8, 16);
    }
}

__global__ __launch_bounds__(256, 1) void gemm_big(
    const fp16* __restrict__ A, int lda,
    const fp16* __restrict__ B, int ldb,
    int K, int Mreal, int Nreal,
    const float* __restrict__ bias, float* __restrict__ C, int ldc,
    float* __restrict__ rowsum, int mode)
{
    extern __shared__ char smem[];
    int tid = threadIdx.x, lane = tid & 31, wid = tid >> 5;
    int wm = wid & 1, wn = wid >> 1;
    int n0 = blockIdx.x * 128, m0 = blockIdx.y * 128;
    int nch = K >> 6;

    uint32_t sb = smem_u32(smem);
    float acc[4][4][4];
#pragma unroll
    for (int i = 0; i < 4; i++)
#pragma unroll
        for (int j = 0; j < 4; j++)
#pragma unroll
            for (int v = 0; v < 4; v++) acc[i][j][v] = 0.f;

    ldstage_b(sb, tid, m0, n0, 0, A, lda, B, ldb, Mreal);
    CP_COMMIT();
    if (nch > 1) ldstage_b(sb + BSTAGE, tid, m0, n0, 64, A, lda, B, ldb, Mreal);
    CP_COMMIT();

    for (int ic = 0; ic < nch; ic++) {
        if (ic + 2 < nch)
            ldstage_b(sb + (uint32_t)((ic + 2) % 3) * BSTAGE, tid, m0, n0,
                      (ic + 2) * 64, A, lda, B, ldb, Mreal);
        CP_COMMIT();
        CP_WAIT(2);
        __syncthreads();
        uint32_t st = sb + (uint32_t)(ic % 3) * BSTAGE;
#pragma unroll
        for (int q = 0; q < 4; q++) {
            uint32_t ah[4][4];
            int arow = wm * 64 + (lane & 15);
            int ach  = q * 32 + ((lane >> 4) << 4);
#pragma unroll
            for (int mt = 0; mt < 4; mt++)
                ldm4(ah[mt], st + SW128((uint32_t)((arow + mt * 16) * 128 + ach)));
            uint32_t bh[2][4];
            int brow = wn * 32 + (lane & 7) + (((lane >> 4) & 1) << 3);
            int bch  = q * 32 + (((lane >> 3) & 1) << 4);
#pragma unroll
            for (int p = 0; p < 2; p++)
                ldm4(bh[p], st + 16384 + SW128((uint32_t)((brow + p * 16) * 128 + bch)));
#pragma unroll
            for (int mt = 0; mt < 4; mt++)
#pragma unroll
                for (int p = 0; p < 2; p++)
#pragma unroll
                    for (int h = 0; h < 2; h++)
                        mma16816(acc[mt][p * 2 + h], ah[mt], &bh[p][h * 2]);
        }
        __syncthreads();
    }

    // epilogue
    int rbase = m0 + wm * 64 + (lane >> 2);
    int cbase = n0 + wn * 32 + (lane & 3) * 2;
    float rs[8];
#pragma unroll
    for (int i = 0; i < 8; i++) rs[i] = 0.f;
#pragma unroll
    for (int mt = 0; mt < 4; mt++)
#pragma unroll
        for (int nt = 0; nt < 4; nt++) {
            int col = cbase + nt * 8;
            int r0 = rbase + mt * 16;
            if (col < Nreal) {
                float ba = bias[col], bb = bias[col + 1];
#pragma unroll
                for (int rp = 0; rp < 2; rp++) {
                    int row = r0 + rp * 8;
                    if (row < Mreal) {
                        float v0 = acc[mt][nt][rp * 2]     + ba;
                        float v1 = acc[mt][nt][rp * 2 + 1] + bb;
                        C[(size_t)row * ldc + col]     = v0;
                        C[(size_t)row * ldc + col + 1] = v1;
                        if (mode == 2) {
                            float s = fexp(v0);
                            if (col + 1 < Nreal) s += fexp(v1);
                            rs[mt * 2 + rp] += s;
                        }
                    }
                }
            }
        }
    if (mode == 2) {
#pragma unroll
        for (int i = 0; i < 8; i++) {
            rs[i] += __shfl_xor_sync(0xffffffffu, rs[i], 1);
            rs[i] += __shfl_xor_sync(0xffffffffu, rs[i], 2);
        }
        if ((lane & 3) == 0) {
#pragma unroll
            for (int mt = 0; mt < 4; mt++)
#pragma unroll
                for (int rp = 0; rp < 2; rp++) {
                    int row = rbase + mt * 16 + rp * 8;
                    if (row < Mreal) atomicAdd(&rowsum[row], rs[mt * 2 + rp]);
                }
        }
    }
}

// ---------------- fused recurrent step: GEMM + K-split reduce + LSTM update ---
// grid (32 ntiles, 1, 4 ksplits), block 256.  A = [h0|h1] split hi/lo, 2-pass.
// B gate-interleaved [4096][K].  Last-arriving CTA per ntile does the update.
#define RSTAGE 32768
__device__ __forceinline__ void ldstage_r(
    uint32_t st, int tid, int n0, int k0,
    const fp16* A0h, const fp16* A0l, const fp16* A1h, const fp16* A1l,
    const fp16* B, int ldb)
{
    const fp16* ah; const fp16* al;
    int kk = k0;
    if (k0 < 1024) { ah = A0h; al = A0l; }
    else           { ah = A1h; al = A1l; kk = k0 - 1024; }
#pragma unroll
    for (int e = tid; e < 512; e += 256) {
        int r = e >> 3, c = e & 7;
        uint32_t sw = SW128((uint32_t)(r * 128 + c * 16));
        size_t off = (size_t)r * 1024 + kk + c * 8;
        cpa16(st + sw,        ah + off, 16);
        cpa16(st + 8192 + sw, al + off, 16);
    }
#pragma unroll
    for (int e = tid; e < 1024; e += 256) {
        int r = e >> 3, c = e & 7;
        uint32_t sw = SW128((uint32_t)(r * 128 + c * 16));
        cpa16(st + 16384 + sw, B + (size_t)(n0 + r) * ldb + k0 + c * 8, 16);
    }
}

__global__ __launch_bounds__(256, 1) void rstep(
    const fp16* __restrict__ A0h, const fp16* __restrict__ A0l,
    const fp16* __restrict__ A1h, const fp16* __restrict__ A1l,
    const fp16* __restrict__ B, int ldb, int kPerSplit,
    const float* __restrict__ addin, int addin_rows,
    fp16* __restrict__ houtH, fp16* __restrict__ houtL,
    float* __restrict__ cst, fp16* __restrict__ h1out,
    float* __restrict__ gp, int* __restrict__ cnt)
{
    extern __shared__ char smem[];
    int tid = threadIdx.x, lane = tid & 31, wn = tid >> 5;
    int ntile = blockIdx.x, z = blockIdx.z;
    int n0 = ntile * 128;
    int kstart = z * kPerSplit;
    int nch = kPerSplit >> 6;

    uint32_t sb = smem_u32(smem);
    float acc[4][2][4];
#pragma unroll
    for (int i = 0; i < 4; i++)
#pragma unroll
        for (int j = 0; j < 2; j++)
#pragma unroll
            for (int v = 0; v < 4; v++) acc[i][j][v] = 0.f;

    ldstage_r(sb, tid, n0, kstart, A0h, A0l, A1h, A1l, B, ldb);
    CP_COMMIT();
    if (nch > 1) ldstage_r(sb + RSTAGE, tid, n0, kstart + 64, A0h, A0l, A1h, A1l, B, ldb);
    CP_COMMIT();

    for (int ic = 0; ic < nch; ic++) {
        if (ic + 2 < nch)
            ldstage_r(sb + (uint32_t)((ic + 2) % 3) * RSTAGE, tid, n0,
                      kstart + (ic + 2) * 64, A0h, A0l, A1h, A1l, B, ldb);
        CP_COMMIT();
        CP_WAIT(2);
        __syncthreads();
        uint32_t st = sb + (uint32_t)(ic % 3) * RSTAGE;
#pragma unroll
        for (int q = 0; q < 4; q++) {
            uint32_t ah[4][4], al[4][4];
            int arow = lane & 15;
            int ach  = q * 32 + ((lane >> 4) << 4);
#pragma unroll
            for (int mt = 0; mt < 4; mt++) {
                uint32_t loc = SW128((uint32_t)((arow + mt * 16) * 128 + ach));
                ldm4(ah[mt], st + loc);
                ldm4(al[mt], st + 8192 + loc);
            }
            uint32_t bh[4];
            int brow = wn * 16 + (lane & 7) + (((lane >> 4) & 1) << 3);
            int bch  = q * 32 + (((lane >> 3) & 1) << 4);
            ldm4(bh, st + 16384 + SW128((uint32_t)(brow * 128 + bch)));
#pragma unroll
            for (int mt = 0; mt < 4; mt++)
#pragma unroll
                for (int h = 0; h < 2; h++) {
                    mma16816(acc[mt][h], ah[mt], &bh[h * 2]);
                    mma16816(acc[mt][h], al[mt], &bh[h * 2]);
                }
        }
        __syncthreads();
    }

    // ---- write partial tile, take ticket ----
    float* tb = gp + ((size_t)(z * 32 + ntile) * 8192);   // [64][128]
    int lrow = lane >> 2;
    int lcol = wn * 16 + (lane & 3) * 2;
#pragma unroll
    for (int mt = 0; mt < 4; mt++)
#pragma unroll
        for (int nt = 0; nt < 2; nt++) {
            int rr = lrow + mt * 16, cc = lcol + nt * 8;
            *(float2*)&tb[rr * 128 + cc]       = make_float2(acc[mt][nt][0], acc[mt][nt][1]);
            *(float2*)&tb[(rr + 8) * 128 + cc] = make_float2(acc[mt][nt][2], acc[mt][nt][3]);
        }
    __syncthreads();
    __shared__ int slast;
    if (tid == 0) {
        __threadfence();
        int tk = atomicAdd(&cnt[ntile], 1);
        slast = (tk == 3);
    }
    __syncthreads();
    if (!slast) return;

    // ---- last CTA: sum other partials + addin, do LSTM update ----
#pragma unroll
    for (int z2 = 0; z2 < 4; z2++) {
        if (z2 == z) continue;
        const float2* ob = (const float2*)(gp + ((size_t)(z2 * 32 + ntile) * 8192));
#pragma unroll
        for (int mt = 0; mt < 4; mt++)
#pragma unroll
            for (int nt = 0; nt < 2; nt++) {
                int rr = lrow + mt * 16, cc = lcol + nt * 8;
                float2 p0 = __ldcg(&ob[(rr * 128 + cc) >> 1]);
                float2 p1 = __ldcg(&ob[((rr + 8) * 128 + cc) >> 1]);
                acc[mt][nt][0] += p0.x; acc[mt][nt][1] += p0.y;
                acc[mt][nt][2] += p1.x; acc[mt][nt][3] += p1.y;
            }
    }
#pragma unroll
    for (int mt = 0; mt < 4; mt++)
#pragma unroll
        for (int nt = 0; nt < 2; nt++) {
            int rr = lrow + mt * 16, cc = n0 + lcol + nt * 8;
            if (addin_rows) {
                float2 a0 = *(const float2*)&addin[(size_t)rr * G4 + cc];
                float2 a1 = *(const float2*)&addin[(size_t)(rr + 8) * G4 + cc];
                acc[mt][nt][0] += a0.x; acc[mt][nt][1] += a0.y;
                acc[mt][nt][2] += a1.x; acc[mt][nt][3] += a1.y;
            } else {
                float2 a0 = *(const float2*)&addin[cc];
                acc[mt][nt][0] += a0.x; acc[mt][nt][1] += a0.y;
                acc[mt][nt][2] += a0.x; acc[mt][nt][3] += a0.y;
            }
        }
    // pair (i,f) with (g,o) via lane^1
#pragma unroll
    for (int mt = 0; mt < 4; mt++)
#pragma unroll
        for (int nt = 0; nt < 2; nt++)
#pragma unroll
            for (int rp = 0; rp < 2; rp++) {
                float gA = acc[mt][nt][rp * 2], gB = acc[mt][nt][rp * 2 + 1];
                float gC = __shfl_xor_sync(0xffffffffu, gA, 1);
                float gD = __shfl_xor_sync(0xffffffffu, gB, 1);
                if ((lane & 1) == 0) {
                    int bb = lrow + mt * 16 + rp * 8;
                    int u = (n0 + lcol + nt * 8) >> 2;
                    int ci = bb * HH + u;
                    float cold = cst[ci];
                    float cn = sigf(gB) * cold + sigf(gA) * tanhf_(gC);
                    float hn = sigf(gD) * tanhf_(cn);
                    cst[ci] = cn;
                    fp16 hi = __float2half_rn(hn);
                    houtH[ci] = hi;
                    houtL[ci] = __float2half_rn(hn - __half2float(hi));
                    if (h1out) h1out[(size_t)bb * (TM1 * HH) + u] = hi;
                }
            }
    __syncthreads();
    if (tid == 0) cnt[ntile] = 0;
}

// ---------------- loss --------------------------------------------------------
__global__ void loss_pick(const float* __restrict__ temp, const int* __restrict__ sent) {
    int idx = blockIdx.x * 256 + threadIdx.x;
    if (idx >= MROWS) return;
    int b = idx / TM1, t = idx - b * TM1;
    int gt = sent[b * TT + t + 1];
    if (gt != 0) {
        float lp = temp[(size_t)idx * VV + gt] - logf(g_rowsum[idx]);
        atomicAdd(&g_lossb[b], lp);
    }
}

__global__ void loss_final(const int* __restrict__ length, float* __restrict__ out) {
    int tid = threadIdx.x;  // 64 threads
    float v = -g_lossb[tid] / (float)length[tid];
#pragma unroll
    for (int o = 16; o; o >>= 1) v += __shfl_xor_sync(0xffffffffu, v, o);
    __shared__ float r2[2];
    if ((tid & 31) == 0) r2[tid >> 5] = v;
    __syncthreads();
    if (tid == 0) out[0] = r2[0] + r2[1];
}

// ---------------- launch ------------------------------------------------------
#define SMEM3 98304   // 3 * 32768

extern "C" void kernel_launch(void* const* d_in, const int* in_sizes, int n_in,
                              void* d_out, int out_size) {
    const int*   sent    = (const int*)  d_in[0];
    const int*   length  = (const int*)  d_in[1];
    const float* wordvec = (const float*)d_in[2];
    const float* w_ih0   = (const float*)d_in[3];
    const float* w_hh0   = (const float*)d_in[4];
    const float* b0      = (const float*)d_in[5];
    const float* w_ih1   = (const float*)d_in[6];
    const float* w_hh1   = (const float*)d_in[7];
    const float* b1      = (const float*)d_in[8];
    const float* w_out   = (const float*)d_in[9];
    const float* b_out   = (const float*)d_in[10];
    float* out = (float*)d_out;

    long long tempoff = (long long)out_size - (long long)MROWS * VV;
    if (tempoff < 0) tempoff = 0;
    float* temp = out + tempoff;

    static int smem_set = 0;
    if (!smem_set) {
        cudaFuncSetAttribute(gemm_big, cudaFuncAttributeMaxDynamicSharedMemorySize, SMEM3);
        cudaFuncSetAttribute(rstep,    cudaFuncAttributeMaxDynamicSharedMemorySize, SMEM3);
        smem_set = 1;
    }

    float *p_pre0, *p_gp0, *p_gp1, *p_c0, *p_c1, *p_b0i, *p_b1i, *p_rowsum;
    fp16 *p_emb, *p_h0H, *p_h0L, *p_h1H, *p_h1L, *p_H1;
    fp16 *p_wih0, *p_whh0, *p_w1, *p_wo;
    int *p_cnt;
    cudaGetSymbolAddress((void**)&p_pre0, g_pre0);
    cudaGetSymbolAddress((void**)&p_gp0,  g_gp0);
    cudaGetSymbolAddress((void**)&p_gp1,  g_gp1);
    cudaGetSymbolAddress((void**)&p_c0,   g_c0);
    cudaGetSymbolAddress((void**)&p_c1,   g_c1);
    cudaGetSymbolAddress((void**)&p_b0i,  g_b0i);
    cudaGetSymbolAddress((void**)&p_b1i,  g_b1i);
    cudaGetSymbolAddress((void**)&p_rowsum, g_rowsum);
    cudaGetSymbolAddress((void**)&p_emb,  g_emb);
    cudaGetSymbolAddress((void**)&p_h0H,  g_h0H);
    cudaGetSymbolAddress((void**)&p_h0L,  g_h0L);
    cudaGetSymbolAddress((void**)&p_h1H,  g_h1H);
    cudaGetSymbolAddress((void**)&p_h1L,  g_h1L);
    cudaGetSymbolAddress((void**)&p_H1,   g_H1);
    cudaGetSymbolAddress((void**)&p_wih0, g_wih0T);
    cudaGetSymbolAddress((void**)&p_whh0, g_whh0T);
    cudaGetSymbolAddress((void**)&p_w1,   g_w1T);
    cudaGetSymbolAddress((void**)&p_wo,   g_woutT);
    cudaGetSymbolAddress((void**)&p_cnt,  g_cnt);

    zero_state<<<512, 256>>>();
    gather_emb<<<(MROWS * KE + 255) / 256, 256>>>(sent, wordvec);

    dim3 pth(32, 8);
    prep_T<<<dim3(KE / 32, G4 / 32), pth>>>(w_ih0, EE, G4, p_wih0, KE, 0, KE, G4, 1);
    prep_T<<<dim3(HH / 32, G4 / 32), pth>>>(w_hh0, HH, G4, p_whh0, HH, 0, HH, G4, 1);
    prep_T<<<dim3(HH / 32, G4 / 32), pth>>>(w_ih1, HH, G4, p_w1, 2048, 0, HH, G4, 1);
    prep_T<<<dim3(HH / 32, G4 / 32), pth>>>(w_hh1, HH, G4, p_w1, 2048, 1024, HH, G4, 1);
    prep_T<<<dim3(HH / 32, NPADV / 32), pth>>>(w_out, HH, VV, p_wo, HH, 0, HH, NPADV, 0);
    prep_bias<<<16, 256>>>(b0, b1);

    // pre0 = emb @ w_ih0 + b0i (interleaved cols)
    gemm_big<<<dim3(G4 / 128, 64), 256, SMEM3>>>(
        p_emb, KE, p_wih0, KE, KE, MROWS, G4, p_b0i, p_pre0, G4, nullptr, 0);

    for (int t = 0; t < TM1; t++) {
        int p = t & 1;
        // layer0: gates = h0 @ whh0 + pre0[t];  writes h0 parity p^1
        rstep<<<dim3(32, 1, 4), 256, SMEM3>>>(
            p_h0H + p * 65536, p_h0L + p * 65536, nullptr, nullptr,
            p_whh0, HH, 256,
            p_pre0 + (size_t)t * 64 * G4, 1,
            p_h0H + (p ^ 1) * 65536, p_h0L + (p ^ 1) * 65536,
            p_c0, nullptr, p_gp0, p_cnt);
        // layer1: gates = [h0(new)|h1(old)] @ w1 + b1i; writes h1 parity p^1, H1
        rstep<<<dim3(32, 1, 4), 256, SMEM3>>>(
            p_h0H + (p ^ 1) * 65536, p_h0L + (p ^ 1) * 65536,
            p_h1H + p * 65536, p_h1L + p * 65536,
            p_w1, 2048, 512,
            p_b1i, 0,
            p_h1H + (p ^ 1) * 65536, p_h1L + (p ^ 1) * 65536,
            p_c1, p_H1 + (size_t)t * HH, p_gp1, p_cnt + 32);
    }

    // logits = H1 @ w_out + b_out; fused exp-rowsum
    gemm_big<<<dim3(NPADV / 128, 64), 256, SMEM3>>>(
        p_H1, HH, p_wo, HH, HH, MROWS, VV, b_out, temp, VV, p_rowsum, 2);

    loss_pick<<<(MROWS + 255) / 256, 256>>>(temp, sent);
    if (tempoff > 0) loss_final<<<1, 64>>>(length, out);
}

// round 6
// speedup vs baseline: 3.3067x; 3.3067x over previous
#include <cuda_runtime.h>
#include <cuda_fp16.h>
#include <cstdint>

#define BB   64
#define TT   128
#define VV   10000
#define EE   300
#define HH   1024
#define G4   4096
#define TM1  127
#define MROWS 8128
#define KE   320        // padded E
#define NPADV 10112     // padded V (79*128)

typedef __half fp16;

// ---------------- scratch (device globals) -----------------------------------
__device__ __align__(16) fp16  g_emb [MROWS * KE];
__device__ __align__(16) float g_pre0[(size_t)MROWS * G4];     // plain gate cols
__device__ __align__(16) float g_gp0 [2 * BB * G4];            // layer0 K-split partials
__device__ __align__(16) float g_gp1 [4 * BB * G4];            // layer1 K-split partials
__device__ __align__(16) float g_c0  [BB * HH];
__device__ __align__(16) float g_c1  [BB * HH];
__device__ __align__(16) fp16  g_h0H [BB * HH];
__device__ __align__(16) fp16  g_h0L [BB * HH];
__device__ __align__(16) fp16  g_h1H [BB * HH];
__device__ __align__(16) fp16  g_h1L [BB * HH];
__device__ __align__(16) fp16  g_H1  [(size_t)MROWS * HH];
__device__ __align__(16) fp16  g_wih0T[G4 * KE];               // [4096][320]
__device__ __align__(16) fp16  g_whh0T[G4 * HH];               // [4096][1024]
__device__ __align__(16) fp16  g_w1T [G4 * 2048];              // [4096][ih1|hh1]
__device__ __align__(16) fp16  g_woutT[(size_t)NPADV * HH];
__device__ __align__(16) float g_rowsum[MROWS];
__device__ float g_lossb[BB];

// ---------------- fast math (FMA-only exp) -----------------------------------
__device__ __forceinline__ float fexp(float x) {
    x = fminf(x, 88.0f);
    if (x < -87.0f) return 0.0f;
    float t = fmaf(x, 1.4426950408889634f, 12582912.0f);
    float n = t - 12582912.0f;
    int   e = __float_as_int(t) - 0x4B400000;
    float r = fmaf(n, -0.693359375f, x);
    r = fmaf(n, 2.1219444e-4f, r);
    float p = fmaf(8.3333333e-3f, r, 4.1666668e-2f);
    p = fmaf(p, r, 1.6666667e-1f);
    p = fmaf(p, r, 0.5f);
    p = fmaf(p, r, 1.0f);
    p = fmaf(p, r, 1.0f);
    return __int_as_float(__float_as_int(p) + (e << 23));
}
__device__ __forceinline__ float sigf(float x)  { return 1.0f / (1.0f + fexp(-x)); }
__device__ __forceinline__ float tanhf_(float x){ return fmaf(2.0f, sigf(2.0f * x), -1.0f); }

// ---------------- ptx helpers -------------------------------------------------
__device__ __forceinline__ uint32_t smem_u32(const void* p) {
    uint32_t a;
    asm("{ .reg .u64 t; cvta.to.shared.u64 t, %1; cvt.u32.u64 %0, t; }" : "=r"(a) : "l"(p));
    return a;
}
__device__ __forceinline__ void cpa16(uint32_t dst, const void* src, int valid) {
    asm volatile("cp.async.cg.shared.global [%0], [%1], 16, %2;"
                 :: "r"(dst), "l"(src), "r"(valid) : "memory");
}
#define CP_COMMIT()  asm volatile("cp.async.commit_group;" ::: "memory")
#define CP_WAIT(n)   asm volatile("cp.async.wait_group %0;" :: "n"(n) : "memory")

__device__ __forceinline__ void ldm4(uint32_t* r, uint32_t addr) {
    asm volatile("ldmatrix.sync.aligned.m8n8.x4.shared.b16 {%0,%1,%2,%3}, [%4];"
                 : "=r"(r[0]), "=r"(r[1]), "=r"(r[2]), "=r"(r[3]) : "r"(addr));
}
__device__ __forceinline__ void mma16816(float* d, const uint32_t* a, const uint32_t* b) {
    asm volatile(
        "mma.sync.aligned.m16n8k16.row.col.f32.f16.f16.f32 "
        "{%0,%1,%2,%3}, {%4,%5,%6,%7}, {%8,%9}, {%0,%1,%2,%3};"
        : "+f"(d[0]), "+f"(d[1]), "+f"(d[2]), "+f"(d[3])
        : "r"(a[0]), "r"(a[1]), "r"(a[2]), "r"(a[3]), "r"(b[0]), "r"(b[1]));
}
#define SW128(x) ((x) ^ (((x) >> 3) & 0x70))

// ---------------- init / gather / prep ---------------------------------------
__global__ void zero_state() {
    int idx = blockIdx.x * 256 + threadIdx.x;        // 65536 threads
    fp16 z = __float2half_rn(0.0f);
    g_h0H[idx] = z; g_h0L[idx] = z; g_h1H[idx] = z; g_h1L[idx] = z;
    g_c0[idx] = 0.f; g_c1[idx] = 0.f;
    if (idx < MROWS) g_rowsum[idx] = 0.f;
    if (idx < BB) g_lossb[idx] = 0.f;
}

__global__ void gather_emb(const int* __restrict__ sent, const float* __restrict__ wordvec) {
    int idx = blockIdx.x * 256 + threadIdx.x;
    if (idx >= MROWS * KE) return;
    int r = idx / KE, k = idx - r * KE;
    int t = r >> 6, b = r & 63;
    float v = 0.f;
    if (k < EE) { int w = sent[b * TT + t]; v = wordvec[(size_t)w * EE + k]; }
    g_emb[idx] = __float2half_rn(v);
}

// transpose: W fp32 [Ksrc, Nsrc] -> O fp16 [Npad][Kpad] at col offset koff
__global__ void prep_T(const float* __restrict__ W, int Ksrc, int Nsrc,
                       fp16* __restrict__ O,
                       int Kpad, int koff, int Kspan, int Npad) {
    __shared__ float ts[32][33];
    int k0 = blockIdx.x * 32, n0 = blockIdx.y * 32;
    int tx = threadIdx.x, ty = threadIdx.y;
#pragma unroll
    for (int i = 0; i < 4; i++) {
        int k = k0 + ty + i * 8, n = n0 + tx;
        float v = (k < Ksrc && n < Nsrc) ? W[(size_t)k * Nsrc + n] : 0.f;
        ts[ty + i * 8][tx] = v;
    }
    __syncthreads();
#pragma unroll
    for (int i = 0; i < 4; i++) {
        int n = n0 + ty + i * 8, k = k0 + tx;
        if (n < Npad && k < Kspan)
            O[(size_t)n * Kpad + koff + k] = __float2half_rn(ts[tx][ty + i * 8]);
    }
}

// ---------------- big GEMM (128x128 tile, 3-stage, single-pass fp16) ----------
// mode 0: C = A@B^T + bias.  mode 2: same + per-row exp-sum into rowsum.
#define BSTAGE 32768
__device__ __forceinline__ void ldstage_b(
    uint32_t st, int tid, int m0, int n0, int k0,
    const fp16* A, int lda, const fp16* B, int ldb, int Mreal)
{
#pragma unroll
    for (int e = tid; e < 1024; e += 256) {
        int r = e >> 3, c = e & 7;
        uint32_t sw = SW128((uint32_t)(r * 128 + c * 16));
        int gr = m0 + r;
        int ok = 16;
        if (gr >= Mreal) { ok = 0; gr = 0; }
        cpa16(st + sw, A + (size_t)gr * lda + k0 + c * 8, ok);
    }
#pragma unroll
    for (int e = tid; e < 1024; e += 256) {
        int r = e >> 3, c = e & 7;
        uint32_t sw = SW128((uint32_t)(r * 128 + c * 16));
        cpa16(st + 16384 + sw, B + (size_t)(n0 + r) * ldb + k0 + c * 8, 16);
    }
}

__global__ __launch_bounds__(256, 1) void gemm_big(
    const fp16* __restrict__ A, int lda,
    const fp16* __restrict__ B, int ldb,
    int K, int Mreal, int Nreal,
    const float* __restrict__ bias, float* __restrict__ C, int ldc,
    float* __restrict__ rowsum, int mode)
{
    extern __shared__ char smem[];
    int tid = threadIdx.x, lane = tid & 31, wid = tid >> 5;
    int wm = wid & 1, wn = wid >> 1;
    int n0 = blockIdx.x * 128, m0 = blockIdx.y * 128;
    int nch = K >> 6;

    uint32_t sb = smem_u32(smem);
    float acc[4][4][4];
#pragma unroll
    for (int i = 0; i < 4; i++)
#pragma unroll
        for (int j = 0; j < 4; j++)
#pragma unroll
            for (int v = 0; v < 4; v++) acc[i][j][v] = 0.f;

    ldstage_b(sb, tid, m0, n0, 0, A, lda, B, ldb, Mreal);
    CP_COMMIT();
    if (nch > 1) ldstage_b(sb + BSTAGE, tid, m0, n0, 64, A, lda, B, ldb, Mreal);
    CP_COMMIT();

    for (int ic = 0; ic < nch; ic++) {
        if (ic + 2 < nch)
            ldstage_b(sb + (uint32_t)((ic + 2) % 3) * BSTAGE, tid, m0, n0,
                      (ic + 2) * 64, A, lda, B, ldb, Mreal);
        CP_COMMIT();
        CP_WAIT(2);
        __syncthreads();
        uint32_t st = sb + (uint32_t)(ic % 3) * BSTAGE;
#pragma unroll
        for (int q = 0; q < 4; q++) {
            uint32_t ah[4][4];
            int arow = wm * 64 + (lane & 15);
            int ach  = q * 32 + ((lane >> 4) << 4);
#pragma unroll
            for (int mt = 0; mt < 4; mt++)
                ldm4(ah[mt], st + SW128((uint32_t)((arow + mt * 16) * 128 + ach)));
            uint32_t bh[2][4];
            int brow = wn * 32 + (lane & 7) + (((lane >> 4) & 1) << 3);
            int bch  = q * 32 + (((lane >> 3) & 1) << 4);
#pragma unroll
            for (int p = 0; p < 2; p++)
                ldm4(bh[p], st + 16384 + SW128((uint32_t)((brow + p * 16) * 128 + bch)));
#pragma unroll
            for (int mt = 0; mt < 4; mt++)
#pragma unroll
                for (int p = 0; p < 2; p++)
#pragma unroll
                    for (int h = 0; h < 2; h++)
                        mma16816(acc[mt][p * 2 + h], ah[mt], &bh[p][h * 2]);
        }
        __syncthreads();
    }

    int rbase = m0 + wm * 64 + (lane >> 2);
    int cbase = n0 + wn * 32 + (lane & 3) * 2;
    float rs[8];
#pragma unroll
    for (int i = 0; i < 8; i++) rs[i] = 0.f;
#pragma unroll
    for (int mt = 0; mt < 4; mt++)
#pragma unroll
        for (int nt = 0; nt < 4; nt++) {
            int col = cbase + nt * 8;
            int r0 = rbase + mt * 16;
            if (col < Nreal) {
                float ba = bias[col], bb = bias[col + 1];
#pragma unroll
                for (int rp = 0; rp < 2; rp++) {
                    int row = r0 + rp * 8;
                    if (row < Mreal) {
                        float v0 = acc[mt][nt][rp * 2]     + ba;
                        float v1 = acc[mt][nt][rp * 2 + 1] + bb;
                        C[(size_t)row * ldc + col]     = v0;
                        C[(size_t)row * ldc + col + 1] = v1;
                        if (mode == 2) {
                            float s = fexp(v0);
                            if (col + 1 < Nreal) s += fexp(v1);
                            rs[mt * 2 + rp] += s;
                        }
                    }
                }
            }
        }
    if (mode == 2) {
#pragma unroll
        for (int i = 0; i < 8; i++) {
            rs[i] += __shfl_xor_sync(0xffffffffu, rs[i], 1);
            rs[i] += __shfl_xor_sync(0xffffffffu, rs[i], 2);
        }
        if ((lane & 3) == 0) {
#pragma unroll
            for (int mt = 0; mt < 4; mt++)
#pragma unroll
                for (int rp = 0; rp < 2; rp++) {
                    int row = rbase + mt * 16 + rp * 8;
                    if (row < Mreal) atomicAdd(&rowsum[row], rs[mt * 2 + rp]);
                }
        }
    }
}

// ---------------- wavefront recurrence GEMM (64x128, 2-pass split-A, 2-stage) -
// grid (32, 1, 6-zoff): z+zoff in {0,1}: layer0 K-slice z*512 of h0@whh0 -> gp0[z]
//                       z+zoff in {2..5}: layer1 K-slice zz*512 of [h0|h1]@w1 -> gp1[zz]
#define RSTAGE 32768
__device__ __forceinline__ void ldstage_r(
    uint32_t st, int tid, int n0, int kA, int kB,
    const fp16* Ah, const fp16* Al, const fp16* B, int ldb)
{
#pragma unroll
    for (int e = tid; e < 512; e += 256) {
        int r = e >> 3, c = e & 7;
        uint32_t sw = SW128((uint32_t)(r * 128 + c * 16));
        size_t off = (size_t)r * 1024 + kA + c * 8;
        cpa16(st + sw,        Ah + off, 16);
        cpa16(st + 8192 + sw, Al + off, 16);
    }
#pragma unroll
    for (int e = tid; e < 1024; e += 256) {
        int r = e >> 3, c = e & 7;
        uint32_t sw = SW128((uint32_t)(r * 128 + c * 16));
        cpa16(st + 16384 + sw, B + (size_t)(n0 + r) * ldb + kB + c * 8, 16);
    }
}

__global__ __launch_bounds__(256, 2) void rgemm(int zoff) {
    extern __shared__ char smem[];
    int tid = threadIdx.x, lane = tid & 31, wn = tid >> 5;
    int n0 = blockIdx.x * 128;
    int z = blockIdx.z + zoff;

    const fp16 *Ah, *Al, *Bp;
    float* gpo;
    int kA, kB, ldb, zi;
    if (z < 2) {
        Ah = g_h0H; Al = g_h0L; kA = z * 512;
        Bp = g_whh0T; ldb = 1024; kB = z * 512;
        gpo = g_gp0; zi = z;
    } else {
        int zz = z - 2;
        if (zz < 2) { Ah = g_h0H; Al = g_h0L; kA = zz * 512; }
        else        { Ah = g_h1H; Al = g_h1L; kA = (zz - 2) * 512; }
        Bp = g_w1T; ldb = 2048; kB = zz * 512;
        gpo = g_gp1; zi = zz;
    }

    uint32_t sb = smem_u32(smem);
    float acc[4][2][4];
#pragma unroll
    for (int i = 0; i < 4; i++)
#pragma unroll
        for (int j = 0; j < 2; j++)
#pragma unroll
            for (int v = 0; v < 4; v++) acc[i][j][v] = 0.f;

    ldstage_r(sb, tid, n0, kA, kB, Ah, Al, Bp, ldb);
    CP_COMMIT();

    for (int ic = 0; ic < 8; ic++) {
        uint32_t st = sb + (uint32_t)(ic & 1) * RSTAGE;
        if (ic + 1 < 8) {
            ldstage_r(sb + (uint32_t)((ic + 1) & 1) * RSTAGE, tid, n0,
                      kA + (ic + 1) * 64, kB + (ic + 1) * 64, Ah, Al, Bp, ldb);
            CP_COMMIT();
            CP_WAIT(1);
        } else {
            CP_WAIT(0);
        }
        __syncthreads();
#pragma unroll
        for (int q = 0; q < 4; q++) {
            uint32_t ah[4][4], al[4][4];
            int arow = lane & 15;
            int ach  = q * 32 + ((lane >> 4) << 4);
#pragma unroll
            for (int mt = 0; mt < 4; mt++) {
                uint32_t loc = SW128((uint32_t)((arow + mt * 16) * 128 + ach));
                ldm4(ah[mt], st + loc);
                ldm4(al[mt], st + 8192 + loc);
            }
            uint32_t bh[4];
            int brow = wn * 16 + (lane & 7) + (((lane >> 4) & 1) << 3);
            int bch  = q * 32 + (((lane >> 3) & 1) << 4);
            ldm4(bh, st + 16384 + SW128((uint32_t)(brow * 128 + bch)));
#pragma unroll
            for (int mt = 0; mt < 4; mt++)
#pragma unroll
                for (int h = 0; h < 2; h++) {
                    mma16816(acc[mt][h], ah[mt], &bh[h * 2]);
                    mma16816(acc[mt][h], al[mt], &bh[h * 2]);
                }
        }
        __syncthreads();
    }

    int rbase = zi * 64 + (lane >> 2);
    int cbase = n0 + wn * 16 + (lane & 3) * 2;
#pragma unroll
    for (int mt = 0; mt < 4; mt++)
#pragma unroll
        for (int nt = 0; nt < 2; nt++) {
            int col = cbase + nt * 8;
            int r0 = rbase + mt * 16;
            gpo[(size_t)r0 * G4 + col]           = acc[mt][nt][0];
            gpo[(size_t)r0 * G4 + col + 1]       = acc[mt][nt][1];
            gpo[(size_t)(r0 + 8) * G4 + col]     = acc[mt][nt][2];
            gpo[(size_t)(r0 + 8) * G4 + col + 1] = acc[mt][nt][3];
        }
}

// ---------------- combined LSTM update: upd0(t+1) || upd1(t) ------------------
// nz0: #gp0 partials for upd0 (0 = prologue, -1 = skip upd0); do1: run upd1(t)
__global__ __launch_bounds__(256) void upd_both(int t, int nz0, int do1,
                                                const float* __restrict__ b1) {
    int gidx = blockIdx.x * 256 + threadIdx.x;   // 131072
    if (gidx < 65536) {
        if (nz0 < 0) return;
        int b = gidx >> 10, h = gidx & 1023;
        const float* pre = g_pre0 + ((size_t)((t + 1) * 64 + b)) * G4;
        float gi = pre[h], gf = pre[1024 + h], gg = pre[2048 + h], go = pre[3072 + h];
        for (int z = 0; z < nz0; z++) {
            const float* gpp = g_gp0 + ((size_t)(z * 64 + b)) * G4;
            gi += gpp[h]; gf += gpp[1024 + h]; gg += gpp[2048 + h]; go += gpp[3072 + h];
        }
        float c = sigf(gf) * g_c0[gidx] + sigf(gi) * tanhf_(gg);
        float hn = sigf(go) * tanhf_(c);
        g_c0[gidx] = c;
        fp16 hi = __float2half_rn(hn);
        g_h0H[gidx] = hi;
        g_h0L[gidx] = __float2half_rn(hn - __half2float(hi));
    } else {
        if (!do1) return;
        int idx = gidx - 65536;
        int b = idx >> 10, h = idx & 1023;
        float gi = b1[h], gf = b1[1024 + h], gg = b1[2048 + h], go = b1[3072 + h];
#pragma unroll
        for (int z = 0; z < 4; z++) {
            const float* gpp = g_gp1 + ((size_t)(z * 64 + b)) * G4;
            gi += gpp[h]; gf += gpp[1024 + h]; gg += gpp[2048 + h]; go += gpp[3072 + h];
        }
        float c = sigf(gf) * g_c1[idx] + sigf(gi) * tanhf_(gg);
        float hn = sigf(go) * tanhf_(c);
        g_c1[idx] = c;
        fp16 hi = __float2half_rn(hn);
        g_h1H[idx] = hi;
        g_h1L[idx] = __float2half_rn(hn - __half2float(hi));
        g_H1[((size_t)b * TM1 + t) * HH + h] = hi;
    }
}

// ---------------- loss --------------------------------------------------------
__global__ void loss_pick(const float* __restrict__ temp, const int* __restrict__ sent) {
    int idx = blockIdx.x * 256 + threadIdx.x;
    if (idx >= MROWS) return;
    int b = idx / TM1, t = idx - b * TM1;
    int gt = sent[b * TT + t + 1];
    if (gt != 0) {
        float lp = temp[(size_t)idx * VV + gt] - logf(g_rowsum[idx]);
        atomicAdd(&g_lossb[b], lp);
    }
}

__global__ void loss_final(const int* __restrict__ length, float* __restrict__ out) {
    int tid = threadIdx.x;  // 64 threads
    float v = -g_lossb[tid] / (float)length[tid];
#pragma unroll
    for (int o = 16; o; o >>= 1) v += __shfl_xor_sync(0xffffffffu, v, o);
    __shared__ float r2[2];
    if ((tid & 31) == 0) r2[tid >> 5] = v;
    __syncthreads();
    if (tid == 0) out[0] = r2[0] + r2[1];
}

// ---------------- launch ------------------------------------------------------
#define SMEMB 98304   // gemm_big: 3 * 32768
#define SMEMR 65536   // rgemm:    2 * 32768

extern "C" void kernel_launch(void* const* d_in, const int* in_sizes, int n_in,
                              void* d_out, int out_size) {
    const int*   sent    = (const int*)  d_in[0];
    const int*   length  = (const int*)  d_in[1];
    const float* wordvec = (const float*)d_in[2];
    const float* w_ih0   = (const float*)d_in[3];
    const float* w_hh0   = (const float*)d_in[4];
    const float* b0      = (const float*)d_in[5];
    const float* w_ih1   = (const float*)d_in[6];
    const float* w_hh1   = (const float*)d_in[7];
    const float* b1      = (const float*)d_in[8];
    const float* w_out   = (const float*)d_in[9];
    const float* b_out   = (const float*)d_in[10];
    float* out = (float*)d_out;

    long long tempoff = (long long)out_size - (long long)MROWS * VV;
    if (tempoff < 0) tempoff = 0;
    float* temp = out + tempoff;

    static int smem_set = 0;
    if (!smem_set) {
        cudaFuncSetAttribute(gemm_big, cudaFuncAttributeMaxDynamicSharedMemorySize, SMEMB);
        cudaFuncSetAttribute(rgemm,    cudaFuncAttributeMaxDynamicSharedMemorySize, SMEMR);
        smem_set = 1;
    }

    float *p_pre0, *p_rowsum;
    fp16 *p_emb, *p_H1, *p_wih0, *p_whh0, *p_w1, *p_wo;
    cudaGetSymbolAddress((void**)&p_pre0, g_pre0);
    cudaGetSymbolAddress((void**)&p_rowsum, g_rowsum);
    cudaGetSymbolAddress((void**)&p_emb,  g_emb);
    cudaGetSymbolAddress((void**)&p_H1,   g_H1);
    cudaGetSymbolAddress((void**)&p_wih0, g_wih0T);
    cudaGetSymbolAddress((void**)&p_whh0, g_whh0T);
    cudaGetSymbolAddress((void**)&p_w1,   g_w1T);
    cudaGetSymbolAddress((void**)&p_wo,   g_woutT);

    zero_state<<<256, 256>>>();
    gather_emb<<<(MROWS * KE + 255) / 256, 256>>>(sent, wordvec);

    dim3 pth(32, 8);
    prep_T<<<dim3(KE / 32, G4 / 32), pth>>>(w_ih0, EE, G4, p_wih0, KE, 0, KE, G4);
    prep_T<<<dim3(HH / 32, G4 / 32), pth>>>(w_hh0, HH, G4, p_whh0, HH, 0, HH, G4);
    prep_T<<<dim3(HH / 32, G4 / 32), pth>>>(w_ih1, HH, G4, p_w1, 2048, 0, HH, G4);
    prep_T<<<dim3(HH / 32, G4 / 32), pth>>>(w_hh1, HH, G4, p_w1, 2048, 1024, HH, G4);
    prep_T<<<dim3(HH / 32, NPADV / 32), pth>>>(w_out, HH, VV, p_wo, HH, 0, HH, NPADV);

    // pre0 = emb @ w_ih0 + b0   [8128,320pad]@[320,4096]
    gemm_big<<<dim3(G4 / 128, 64), 256, SMEMB>>>(
        p_emb, KE, p_wih0, KE, KE, MROWS, G4, b0, p_pre0, G4, nullptr, 0);

    // prologue: h0(0) from pre0[0] only
    upd_both<<<512, 256>>>(-1, 0, 0, b1);

    // wavefront: gemm0(s+1) || gemm1(s), then upd0(s+1) || upd1(s)
    for (int s = 0; s < TM1 - 1; s++) {
        rgemm<<<dim3(32, 1, 6), 256, SMEMR>>>(0);
        upd_both<<<512, 256>>>(s, 2, 1, b1);
    }
    // epilogue: gemm1(126) + upd1(126)
    rgemm<<<dim3(32, 1, 4), 256, SMEMR>>>(2);
    upd_both<<<512, 256>>>(TM1 - 1, -1, 1, b1);

    // logits = H1 @ w_out + b_out; fused exp-rowsum
    gemm_big<<<dim3(NPADV / 128, 64), 256, SMEMB>>>(
        p_H1, HH, p_wo, HH, HH, MROWS, VV, b_out, temp, VV, p_rowsum, 2);

    loss_pick<<<(MROWS + 255) / 256, 256>>>(temp, sent);
    if (tempoff > 0) loss_final<<<1, 64>>>(length, out);
}

// round 7
// speedup vs baseline: 4.2866x; 1.2963x over previous
#include <cuda_runtime.h>
#include <cuda_fp16.h>
#include <cstdint>

#define BB   64
#define TT   128
#define VV   10000
#define EE   300
#define HH   1024
#define G4   4096
#define TM1  127
#define MROWS 8128
#define KE   320        // padded E
#define NPADV 10112     // padded V (79*128)

typedef __half fp16;

// ---------------- scratch (device globals) -----------------------------------
__device__ __align__(16) fp16  g_emb [MROWS * KE];
__device__ __align__(16) float g_pre0[(size_t)MROWS * G4];     // plain gate cols
__device__ __align__(16) float g_gp0 [2 * BB * G4];            // layer0 K-split partials
__device__ __align__(16) float g_gp1 [4 * BB * G4];            // layer1 K-split partials
__device__ __align__(16) float g_c0  [BB * HH];
__device__ __align__(16) float g_c1  [BB * HH];
__device__ __align__(16) fp16  g_h0H [BB * HH];
__device__ __align__(16) fp16  g_h1H [BB * HH];
__device__ __align__(16) fp16  g_H1  [(size_t)MROWS * HH];
__device__ __align__(16) fp16  g_wih0T[G4 * KE];               // [4096][320]
__device__ __align__(16) fp16  g_whh0T[G4 * HH];               // [4096][1024]
__device__ __align__(16) fp16  g_w1T [G4 * 2048];              // [4096][ih1|hh1]
__device__ __align__(16) fp16  g_woutT[(size_t)NPADV * HH];
__device__ __align__(16) float g_rowsum[MROWS];
__device__ float g_lossb[BB];

// ---------------- fast math (FMA-only exp) -----------------------------------
__device__ __forceinline__ float fexp(float x) {
    x = fminf(x, 88.0f);
    if (x < -87.0f) return 0.0f;
    float t = fmaf(x, 1.4426950408889634f, 12582912.0f);
    float n = t - 12582912.0f;
    int   e = __float_as_int(t) - 0x4B400000;
    float r = fmaf(n, -0.693359375f, x);
    r = fmaf(n, 2.1219444e-4f, r);
    float p = fmaf(8.3333333e-3f, r, 4.1666668e-2f);
    p = fmaf(p, r, 1.6666667e-1f);
    p = fmaf(p, r, 0.5f);
    p = fmaf(p, r, 1.0f);
    p = fmaf(p, r, 1.0f);
    return __int_as_float(__float_as_int(p) + (e << 23));
}
__device__ __forceinline__ float sigf(float x)  { return 1.0f / (1.0f + fexp(-x)); }
__device__ __forceinline__ float tanhf_(float x){ return fmaf(2.0f, sigf(2.0f * x), -1.0f); }

// ---------------- ptx helpers -------------------------------------------------
__device__ __forceinline__ uint32_t smem_u32(const void* p) {
    uint32_t a;
    asm("{ .reg .u64 t; cvta.to.shared.u64 t, %1; cvt.u32.u64 %0, t; }" : "=r"(a) : "l"(p));
    return a;
}
__device__ __forceinline__ void cpa16(uint32_t dst, const void* src, int valid) {
    asm volatile("cp.async.cg.shared.global [%0], [%1], 16, %2;"
                 :: "r"(dst), "l"(src), "r"(valid) : "memory");
}
#define CP_COMMIT()  asm volatile("cp.async.commit_group;" ::: "memory")
#define CP_WAIT(n)   asm volatile("cp.async.wait_group %0;" :: "n"(n) : "memory")

__device__ __forceinline__ void ldm4(uint32_t* r, uint32_t addr) {
    asm volatile("ldmatrix.sync.aligned.m8n8.x4.shared.b16 {%0,%1,%2,%3}, [%4];"
                 : "=r"(r[0]), "=r"(r[1]), "=r"(r[2]), "=r"(r[3]) : "r"(addr));
}
__device__ __forceinline__ void mma16816(float* d, const uint32_t* a, const uint32_t* b) {
    asm volatile(
        "mma.sync.aligned.m16n8k16.row.col.f32.f16.f16.f32 "
        "{%0,%1,%2,%3}, {%4,%5,%6,%7}, {%8,%9}, {%0,%1,%2,%3};"
        : "+f"(d[0]), "+f"(d[1]), "+f"(d[2]), "+f"(d[3])
        : "r"(a[0]), "r"(a[1]), "r"(a[2]), "r"(a[3]), "r"(b[0]), "r"(b[1]));
}
#define SW128(x) ((x) ^ (((x) >> 3) & 0x70))

// ---------------- init / gather / prep ---------------------------------------
__global__ void zero_state() {
    int idx = blockIdx.x * 256 + threadIdx.x;        // 65536 threads
    fp16 z = __float2half_rn(0.0f);
    g_h0H[idx] = z; g_h1H[idx] = z;
    g_c0[idx] = 0.f; g_c1[idx] = 0.f;
    if (idx < MROWS) g_rowsum[idx] = 0.f;
    if (idx < BB) g_lossb[idx] = 0.f;
}

__global__ void gather_emb(const int* __restrict__ sent, const float* __restrict__ wordvec) {
    int idx = blockIdx.x * 256 + threadIdx.x;
    if (idx >= MROWS * KE) return;
    int r = idx / KE, k = idx - r * KE;
    int t = r >> 6, b = r & 63;
    float v = 0.f;
    if (k < EE) { int w = sent[b * TT + t]; v = wordvec[(size_t)w * EE + k]; }
    g_emb[idx] = __float2half_rn(v);
}

// transpose: W fp32 [Ksrc, Nsrc] -> O fp16 [Npad][Kpad] at col offset koff
__global__ void prep_T(const float* __restrict__ W, int Ksrc, int Nsrc,
                       fp16* __restrict__ O,
                       int Kpad, int koff, int Kspan, int Npad) {
    __shared__ float ts[32][33];
    int k0 = blockIdx.x * 32, n0 = blockIdx.y * 32;
    int tx = threadIdx.x, ty = threadIdx.y;
#pragma unroll
    for (int i = 0; i < 4; i++) {
        int k = k0 + ty + i * 8, n = n0 + tx;
        float v = (k < Ksrc && n < Nsrc) ? W[(size_t)k * Nsrc + n] : 0.f;
        ts[ty + i * 8][tx] = v;
    }
    __syncthreads();
#pragma unroll
    for (int i = 0; i < 4; i++) {
        int n = n0 + ty + i * 8, k = k0 + tx;
        if (n < Npad && k < Kspan)
            O[(size_t)n * Kpad + koff + k] = __float2half_rn(ts[tx][ty + i * 8]);
    }
}

// ---------------- big GEMM (128x128 tile, 3-stage, single-pass fp16) ----------
// mode 0: C = A@B^T + bias.  mode 2: same + per-row exp-sum into rowsum.
#define BSTAGE 32768
__device__ __forceinline__ void ldstage_b(
    uint32_t st, int tid, int m0, int n0, int k0,
    const fp16* A, int lda, const fp16* B, int ldb, int Mreal)
{
#pragma unroll
    for (int e = tid; e < 1024; e += 256) {
        int r = e >> 3, c = e & 7;
        uint32_t sw = SW128((uint32_t)(r * 128 + c * 16));
        int gr = m0 + r;
        int ok = 16;
        if (gr >= Mreal) { ok = 0; gr = 0; }
        cpa16(st + sw, A + (size_t)gr * lda + k0 + c * 8, ok);
    }
#pragma unroll
    for (int e = tid; e < 1024; e += 256) {
        int r = e >> 3, c = e & 7;
        uint32_t sw = SW128((uint32_t)(r * 128 + c * 16));
        cpa16(st + 16384 + sw, B + (size_t)(n0 + r) * ldb + k0 + c * 8, 16);
    }
}

__global__ __launch_bounds__(256, 1) void gemm_big(
    const fp16* __restrict__ A, int lda,
    const fp16* __restrict__ B, int ldb,
    int K, int Mreal, int Nreal,
    const float* __restrict__ bias, float* __restrict__ C, int ldc,
    float* __restrict__ rowsum, int mode)
{
    extern __shared__ char smem[];
    int tid = threadIdx.x, lane = tid & 31, wid = tid >> 5;
    int wm = wid & 1, wn = wid >> 1;
    int n0 = blockIdx.x * 128, m0 = blockIdx.y * 128;
    int nch = K >> 6;

    uint32_t sb = smem_u32(smem);
    float acc[4][4][4];
#pragma unroll
    for (int i = 0; i < 4; i++)
#pragma unroll
        for (int j = 0; j < 4; j++)
#pragma unroll
            for (int v = 0; v < 4; v++) acc[i][j][v] = 0.f;

    ldstage_b(sb, tid, m0, n0, 0, A, lda, B, ldb, Mreal);
    CP_COMMIT();
    if (nch > 1) ldstage_b(sb + BSTAGE, tid, m0, n0, 64, A, lda, B, ldb, Mreal);
    CP_COMMIT();

    for (int ic = 0; ic < nch; ic++) {
        if (ic + 2 < nch)
            ldstage_b(sb + (uint32_t)((ic + 2) % 3) * BSTAGE, tid, m0, n0,
                      (ic + 2) * 64, A, lda, B, ldb, Mreal);
        CP_COMMIT();
        CP_WAIT(2);
        __syncthreads();
        uint32_t st = sb + (uint32_t)(ic % 3) * BSTAGE;
#pragma unroll
        for (int q = 0; q < 4; q++) {
            uint32_t ah[4][4];
            int arow = wm * 64 + (lane & 15);
            int ach  = q * 32 + ((lane >> 4) << 4);
#pragma unroll
            for (int mt = 0; mt < 4; mt++)
                ldm4(ah[mt], st + SW128((uint32_t)((arow + mt * 16) * 128 + ach)));
            uint32_t bh[2][4];
            int brow = wn * 32 + (lane & 7) + (((lane >> 4) & 1) << 3);
            int bch  = q * 32 + (((lane >> 3) & 1) << 4);
#pragma unroll
            for (int p = 0; p < 2; p++)
                ldm4(bh[p], st + 16384 + SW128((uint32_t)((brow + p * 16) * 128 + bch)));
#pragma unroll
            for (int mt = 0; mt < 4; mt++)
#pragma unroll
                for (int p = 0; p < 2; p++)
#pragma unroll
                    for (int h = 0; h < 2; h++)
                        mma16816(acc[mt][p * 2 + h], ah[mt], &bh[p][h * 2]);
        }
        __syncthreads();
    }

    int rbase = m0 + wm * 64 + (lane >> 2);
    int cbase = n0 + wn * 32 + (lane & 3) * 2;
    float rs[8];
#pragma unroll
    for (int i = 0; i < 8; i++) rs[i] = 0.f;
#pragma unroll
    for (int mt = 0; mt < 4; mt++)
#pragma unroll
        for (int nt = 0; nt < 4; nt++) {
            int col = cbase + nt * 8;
            int r0 = rbase + mt * 16;
            if (col < Nreal) {
                float ba = bias[col], bb = bias[col + 1];
#pragma unroll
                for (int rp = 0; rp < 2; rp++) {
                    int row = r0 + rp * 8;
                    if (row < Mreal) {
                        float v0 = acc[mt][nt][rp * 2]     + ba;
                        float v1 = acc[mt][nt][rp * 2 + 1] + bb;
                        C[(size_t)row * ldc + col]     = v0;
                        C[(size_t)row * ldc + col + 1] = v1;
                        if (mode == 2) {
                            float s = fexp(v0);
                            if (col + 1 < Nreal) s += fexp(v1);
                            rs[mt * 2 + rp] += s;
                        }
                    }
                }
            }
        }
    if (mode == 2) {
#pragma unroll
        for (int i = 0; i < 8; i++) {
            rs[i] += __shfl_xor_sync(0xffffffffu, rs[i], 1);
            rs[i] += __shfl_xor_sync(0xffffffffu, rs[i], 2);
        }
        if ((lane & 3) == 0) {
#pragma unroll
            for (int mt = 0; mt < 4; mt++)
#pragma unroll
                for (int rp = 0; rp < 2; rp++) {
                    int row = rbase + mt * 16 + rp * 8;
                    if (row < Mreal) atomicAdd(&rowsum[row], rs[mt * 2 + rp]);
                }
        }
    }
}

// ---------------- wavefront recurrence GEMM (64x128, single-pass, 3-stage) ----
// grid (32, 1, 6-zoff): z+zoff in {0,1}: layer0 K-slice z*512 of h0@whh0 -> gp0[z]
//                       z+zoff in {2..5}: layer1 K-slice zz*512 of [h0|h1]@w1 -> gp1[zz]
#define RSTAGE 24576
__device__ __forceinline__ void ldstage_r(
    uint32_t st, int tid, int n0, int kA, int kB,
    const fp16* Ah, const fp16* B, int ldb)
{
#pragma unroll
    for (int e = tid; e < 512; e += 256) {
        int r = e >> 3, c = e & 7;
        uint32_t sw = SW128((uint32_t)(r * 128 + c * 16));
        cpa16(st + sw, Ah + (size_t)r * 1024 + kA + c * 8, 16);
    }
#pragma unroll
    for (int e = tid; e < 1024; e += 256) {
        int r = e >> 3, c = e & 7;
        uint32_t sw = SW128((uint32_t)(r * 128 + c * 16));
        cpa16(st + 8192 + sw, B + (size_t)(n0 + r) * ldb + kB + c * 8, 16);
    }
}

__global__ __launch_bounds__(256, 2) void rgemm(int zoff) {
    extern __shared__ char smem[];
    int tid = threadIdx.x, lane = tid & 31, wn = tid >> 5;
    int n0 = blockIdx.x * 128;
    int z = blockIdx.z + zoff;

    const fp16 *Ah, *Bp;
    float* gpo;
    int kA, kB, ldb, zi;
    if (z < 2) {
        Ah = g_h0H; kA = z * 512;
        Bp = g_whh0T; ldb = 1024; kB = z * 512;
        gpo = g_gp0; zi = z;
    } else {
        int zz = z - 2;
        if (zz < 2) { Ah = g_h0H; kA = zz * 512; }
        else        { Ah = g_h1H; kA = (zz - 2) * 512; }
        Bp = g_w1T; ldb = 2048; kB = zz * 512;
        gpo = g_gp1; zi = zz;
    }

    uint32_t sb = smem_u32(smem);
    float acc[4][2][4];
#pragma unroll
    for (int i = 0; i < 4; i++)
#pragma unroll
        for (int j = 0; j < 2; j++)
#pragma unroll
            for (int v = 0; v < 4; v++) acc[i][j][v] = 0.f;

    ldstage_r(sb, tid, n0, kA, kB, Ah, Bp, ldb);
    CP_COMMIT();
    ldstage_r(sb + RSTAGE, tid, n0, kA + 64, kB + 64, Ah, Bp, ldb);
    CP_COMMIT();

    for (int ic = 0; ic < 8; ic++) {
        if (ic + 2 < 8)
            ldstage_r(sb + (uint32_t)((ic + 2) % 3) * RSTAGE, tid, n0,
                      kA + (ic + 2) * 64, kB + (ic + 2) * 64, Ah, Bp, ldb);
        CP_COMMIT();
        CP_WAIT(2);
        __syncthreads();
        uint32_t st = sb + (uint32_t)(ic % 3) * RSTAGE;
#pragma unroll
        for (int q = 0; q < 4; q++) {
            uint32_t ah[4][4];
            int arow = lane & 15;
            int ach  = q * 32 + ((lane >> 4) << 4);
#pragma unroll
            for (int mt = 0; mt < 4; mt++)
                ldm4(ah[mt], st + SW128((uint32_t)((arow + mt * 16) * 128 + ach)));
            uint32_t bh[4];
            int brow = wn * 16 + (lane & 7) + (((lane >> 4) & 1) << 3);
            int bch  = q * 32 + (((lane >> 3) & 1) << 4);
            ldm4(bh, st + 8192 + SW128((uint32_t)(brow * 128 + bch)));
#pragma unroll
            for (int mt = 0; mt < 4; mt++)
#pragma unroll
                for (int h = 0; h < 2; h++)
                    mma16816(acc[mt][h], ah[mt], &bh[h * 2]);
        }
        __syncthreads();
    }

    int rbase = zi * 64 + (lane >> 2);
    int cbase = n0 + wn * 16 + (lane & 3) * 2;
#pragma unroll
    for (int mt = 0; mt < 4; mt++)
#pragma unroll
        for (int nt = 0; nt < 2; nt++) {
            int col = cbase + nt * 8;
            int r0 = rbase + mt * 16;
            gpo[(size_t)r0 * G4 + col]           = acc[mt][nt][0];
            gpo[(size_t)r0 * G4 + col + 1]       = acc[mt][nt][1];
            gpo[(size_t)(r0 + 8) * G4 + col]     = acc[mt][nt][2];
            gpo[(size_t)(r0 + 8) * G4 + col + 1] = acc[mt][nt][3];
        }
}

// ---------------- combined LSTM update: upd0(t+1) || upd1(t) ------------------
// nz0: #gp0 partials for upd0 (0 = prologue, -1 = skip upd0); do1: run upd1(t)
__global__ __launch_bounds__(256) void upd_both(int t, int nz0, int do1,
                                                const float* __restrict__ b1) {
    int gidx = blockIdx.x * 256 + threadIdx.x;   // 131072
    if (gidx < 65536) {
        if (nz0 < 0) return;
        int b = gidx >> 10, h = gidx & 1023;
        const float* pre = g_pre0 + ((size_t)((t + 1) * 64 + b)) * G4;
        float gi = pre[h], gf = pre[1024 + h], gg = pre[2048 + h], go = pre[3072 + h];
        for (int z = 0; z < nz0; z++) {
            const float* gpp = g_gp0 + ((size_t)(z * 64 + b)) * G4;
            gi += gpp[h]; gf += gpp[1024 + h]; gg += gpp[2048 + h]; go += gpp[3072 + h];
        }
        float c = sigf(gf) * g_c0[gidx] + sigf(gi) * tanhf_(gg);
        float hn = sigf(go) * tanhf_(c);
        g_c0[gidx] = c;
        g_h0H[gidx] = __float2half_rn(hn);
    } else {
        if (!do1) return;
        int idx = gidx - 65536;
        int b = idx >> 10, h = idx & 1023;
        float gi = b1[h], gf = b1[1024 + h], gg = b1[2048 + h], go = b1[3072 + h];
#pragma unroll
        for (int z = 0; z < 4; z++) {
            const float* gpp = g_gp1 + ((size_t)(z * 64 + b)) * G4;
            gi += gpp[h]; gf += gpp[1024 + h]; gg += gpp[2048 + h]; go += gpp[3072 + h];
        }
        float c = sigf(gf) * g_c1[idx] + sigf(gi) * tanhf_(gg);
        float hn = sigf(go) * tanhf_(c);
        g_c1[idx] = c;
        fp16 hi = __float2half_rn(hn);
        g_h1H[idx] = hi;
        g_H1[((size_t)b * TM1 + t) * HH + h] = hi;
    }
}

// ---------------- loss --------------------------------------------------------
__global__ void loss_pick(const float* __restrict__ temp, const int* __restrict__ sent) {
    int idx = blockIdx.x * 256 + threadIdx.x;
    if (idx >= MROWS) return;
    int b = idx / TM1, t = idx - b * TM1;
    int gt = sent[b * TT + t + 1];
    if (gt != 0) {
        float lp = temp[(size_t)idx * VV + gt] - logf(g_rowsum[idx]);
        atomicAdd(&g_lossb[b], lp);
    }
}

__global__ void loss_final(const int* __restrict__ length, float* __restrict__ out) {
    int tid = threadIdx.x;  // 64 threads
    float v = -g_lossb[tid] / (float)length[tid];
#pragma unroll
    for (int o = 16; o; o >>= 1) v += __shfl_xor_sync(0xffffffffu, v, o);
    __shared__ float r2[2];
    if ((tid & 31) == 0) r2[tid >> 5] = v;
    __syncthreads();
    if (tid == 0) out[0] = r2[0] + r2[1];
}

// ---------------- launch ------------------------------------------------------
#define SMEMB 98304   // gemm_big: 3 * 32768
#define SMEMR 73728   // rgemm:    3 * 24576

extern "C" void kernel_launch(void* const* d_in, const int* in_sizes, int n_in,
                              void* d_out, int out_size) {
    const int*   sent    = (const int*)  d_in[0];
    const int*   length  = (const int*)  d_in[1];
    const float* wordvec = (const float*)d_in[2];
    const float* w_ih0   = (const float*)d_in[3];
    const float* w_hh0   = (const float*)d_in[4];
    const float* b0      = (const float*)d_in[5];
    const float* w_ih1   = (const float*)d_in[6];
    const float* w_hh1   = (const float*)d_in[7];
    const float* b1      = (const float*)d_in[8];
    const float* w_out   = (const float*)d_in[9];
    const float* b_out   = (const float*)d_in[10];
    float* out = (float*)d_out;

    long long tempoff = (long long)out_size - (long long)MROWS * VV;
    if (tempoff < 0) tempoff = 0;
    float* temp = out + tempoff;

    static int smem_set = 0;
    if (!smem_set) {
        cudaFuncSetAttribute(gemm_big, cudaFuncAttributeMaxDynamicSharedMemorySize, SMEMB);
        cudaFuncSetAttribute(rgemm,    cudaFuncAttributeMaxDynamicSharedMemorySize, SMEMR);
        smem_set = 1;
    }

    float *p_pre0, *p_rowsum;
    fp16 *p_emb, *p_H1, *p_wih0, *p_whh0, *p_w1, *p_wo;
    cudaGetSymbolAddress((void**)&p_pre0, g_pre0);
    cudaGetSymbolAddress((void**)&p_rowsum, g_rowsum);
    cudaGetSymbolAddress((void**)&p_emb,  g_emb);
    cudaGetSymbolAddress((void**)&p_H1,   g_H1);
    cudaGetSymbolAddress((void**)&p_wih0, g_wih0T);
    cudaGetSymbolAddress((void**)&p_whh0, g_whh0T);
    cudaGetSymbolAddress((void**)&p_w1,   g_w1T);
    cudaGetSymbolAddress((void**)&p_wo,   g_woutT);

    zero_state<<<256, 256>>>();
    gather_emb<<<(MROWS * KE + 255) / 256, 256>>>(sent, wordvec);

    dim3 pth(32, 8);
    prep_T<<<dim3(KE / 32, G4 / 32), pth>>>(w_ih0, EE, G4, p_wih0, KE, 0, KE, G4);
    prep_T<<<dim3(HH / 32, G4 / 32), pth>>>(w_hh0, HH, G4, p_whh0, HH, 0, HH, G4);
    prep_T<<<dim3(HH / 32, G4 / 32), pth>>>(w_ih1, HH, G4, p_w1, 2048, 0, HH, G4);
    prep_T<<<dim3(HH / 32, G4 / 32), pth>>>(w_hh1, HH, G4, p_w1, 2048, 1024, HH, G4);
    prep_T<<<dim3(HH / 32, NPADV / 32), pth>>>(w_out, HH, VV, p_wo, HH, 0, HH, NPADV);

    // pre0 = emb @ w_ih0 + b0   [8128,320pad]@[320,4096]
    gemm_big<<<dim3(G4 / 128, 64), 256, SMEMB>>>(
        p_emb, KE, p_wih0, KE, KE, MROWS, G4, b0, p_pre0, G4, nullptr, 0);

    // prologue: h0(0) from pre0[0] only
    upd_both<<<512, 256>>>(-1, 0, 0, b1);

    // wavefront: gemm0(s+1) || gemm1(s), then upd0(s+1) || upd1(s)
    for (int s = 0; s < TM1 - 1; s++) {
        rgemm<<<dim3(32, 1, 6), 256, SMEMR>>>(0);
        upd_both<<<512, 256>>>(s, 2, 1, b1);
    }
    // epilogue: gemm1(126) + upd1(126)
    rgemm<<<dim3(32, 1, 4), 256, SMEMR>>>(2);
    upd_both<<<512, 256>>>(TM1 - 1, -1, 1, b1);

    // logits = H1 @ w_out + b_out; fused exp-rowsum
    gemm_big<<<dim3(NPADV / 128, 64), 256, SMEMB>>>(
        p_H1, HH, p_wo, HH, HH, MROWS, VV, b_out, temp, VV, p_rowsum, 2);

    loss_pick<<<(MROWS + 255) / 256, 256>>>(temp, sent);
    if (tempoff > 0) loss_final<<<1, 64>>>(length, out);
}